// round 2
// baseline (speedup 1.0000x reference)
#include <cuda_runtime.h>
#include <math.h>

// LWM cross attention, fully fused: per-window 1x1-conv GEMMs (q, kv) +
// linear-attention style epilogue. One CTA per 16x16 window.

namespace {
constexpr int Bn    = 8;
constexpr int C     = 128;
constexpr int Hdim  = 256;
constexpr int Wdim  = 256;
constexpr int NHm   = 8;
constexpr int D     = 16;     // head dim
constexpr int WSz   = 16;     // window size
constexpr int NPix  = 256;    // pixels per window
constexpr int HW    = 16;     // windows per spatial dim
constexpr int NWin  = Bn * HW * HW;  // 2048
constexpr int THREADS = 512;
constexpr float EPSf = 1e-6f;

constexpr int KVH_STRIDE = 260;  // row stride for 32x256 head buffer (16B-aligned rows, 4-way-max store conflicts)
constexpr int WS_STRIDE  = 129;  // row stride for weight stage (conflict-free per-j reads)

// shared memory layout (in floats)
constexpr int OFF_XS    = 0;                        // x tile [128][256]
constexpr int OFF_KVH   = OFF_XS + C * NPix;        // head buffer [32][260]
constexpr int OFF_WSA   = OFF_KVH + 32 * KVH_STRIDE;// weight stage [32][129]
constexpr int OFF_INV   = OFF_WSA + 32 * WS_STRIDE; // per-pixel 1/||k|| [256]
constexpr int OFF_KVACC = OFF_INV + NPix;           // kv_acc [8][16][16]
constexpr int OFF_KSUM  = OFF_KVACC + NHm * D * D;  // ksum [8][16]
constexpr int OFF_VSUM  = OFF_KSUM + NHm * D;       // vsum [8][16]
constexpr int SMEM_FLOATS = OFF_VSUM + NHm * D;     // = 47776
constexpr int SMEM_BYTES  = SMEM_FLOATS * 4;        // = 191104
}

__global__ void __launch_bounds__(THREADS, 1)
lwm_kernel(const float* __restrict__ x1, const float* __restrict__ x2,
           const float* __restrict__ Wq, const float* __restrict__ Wkv,
           float* __restrict__ out)
{
    extern __shared__ float sm[];
    float* xs    = sm + OFF_XS;
    float* kvh   = sm + OFF_KVH;
    float* wsa   = sm + OFF_WSA;
    float* invb  = sm + OFF_INV;
    float* kvacc = sm + OFF_KVACC;
    float* ksum  = sm + OFF_KSUM;
    float* vsum  = sm + OFF_VSUM;

    const int win = blockIdx.x;
    const int wx  = win & 15;
    const int wy  = (win >> 4) & 15;
    const int b   = win >> 8;
    const int t   = threadIdx.x;

    // global base of window pixel (r=0,s=0), channel 0.
    // addr(b,c,h,w) = ((b*C + c)*H + h)*W + w
    const size_t base = (size_t)b * (C * Hdim * Wdim)
                      + (size_t)(wy * WSz) * Wdim + (size_t)(wx * WSz);
    const int CH_STRIDE = Hdim * Wdim;  // 65536

    // ---- tile loader: x[c][n] for this window, float4 vectorized ----
    auto load_tile = [&](const float* __restrict__ src) {
        for (int idx = t; idx < (C * NPix) / 4; idx += THREADS) {
            int c  = idx >> 6;           // 0..127
            int n4 = (idx & 63) << 2;    // pixel index, multiple of 4
            int r  = n4 >> 4, s = n4 & 15;
            float4 v = *reinterpret_cast<const float4*>(
                src + base + (size_t)c * CH_STRIDE + r * Wdim + s);
            *reinterpret_cast<float4*>(xs + c * NPix + n4) = v;
        }
    };

    // =============== Phase A: K/V per head -> summaries ===============
    load_tile(x2);

    for (int h = 0; h < NHm; ++h) {
        // stage 32 weight rows (16 K rows + 16 V rows) for this head
        for (int idx = t; idx < 32 * C; idx += THREADS) {
            int j = idx >> 7, c = idx & 127;
            int row = (j < 16) ? (h * 16 + j) : (C + h * 16 + (j - 16));
            wsa[j * WS_STRIDE + c] = Wkv[row * C + c];
        }
        __syncthreads();

        // GEMM: kv[j][n] = sum_c W[j][c] * x2[c][n]
        {
            const int j  = t & 31;
            const int ng = t >> 5;  // 0..15, 16 pixels each
            float acc[16];
#pragma unroll
            for (int p = 0; p < 16; ++p) acc[p] = 0.f;
            const float* wrow  = wsa + j * WS_STRIDE;
            const float* xbase = xs + ng * 16;
#pragma unroll 4
            for (int c = 0; c < C; ++c) {
                float wv = wrow[c];
                const float4* xp = reinterpret_cast<const float4*>(xbase + c * NPix);
                float4 a0 = xp[0], a1 = xp[1], a2 = xp[2], a3 = xp[3];
                acc[0]  += wv * a0.x; acc[1]  += wv * a0.y; acc[2]  += wv * a0.z; acc[3]  += wv * a0.w;
                acc[4]  += wv * a1.x; acc[5]  += wv * a1.y; acc[6]  += wv * a1.z; acc[7]  += wv * a1.w;
                acc[8]  += wv * a2.x; acc[9]  += wv * a2.y; acc[10] += wv * a2.z; acc[11] += wv * a2.w;
                acc[12] += wv * a3.x; acc[13] += wv * a3.y; acc[14] += wv * a3.z; acc[15] += wv * a3.w;
            }
            float* kd = kvh + j * KVH_STRIDE + ng * 16;
#pragma unroll
            for (int p = 0; p < 16; ++p) kd[p] = acc[p];
        }
        __syncthreads();

        // per-pixel inverse norm of k column (over d=16)
        if (t < NPix) {
            float ss = 0.f;
#pragma unroll
            for (int dd = 0; dd < 16; ++dd) {
                float kk = kvh[dd * KVH_STRIDE + t];
                ss += kk * kk;
            }
            invb[t] = rsqrtf(ss);
        }
        __syncthreads();

        // kv_acc[m][c] = sum_n k_norm[m,n] * v[c,n]; ksum, vsum folded in
        if (t < 256) {
            const int m  = t >> 4;
            const int cc = t & 15;
            const float4* kp = reinterpret_cast<const float4*>(kvh + m * KVH_STRIDE);
            const float4* vp = reinterpret_cast<const float4*>(kvh + (16 + cc) * KVH_STRIDE);
            const float4* ip = reinterpret_cast<const float4*>(invb);
            float a = 0.f, ks = 0.f, vs = 0.f;
#pragma unroll 4
            for (int qn = 0; qn < 64; ++qn) {
                float4 kk = kp[qn], vv = vp[qn], iv = ip[qn];
                float k0 = kk.x * iv.x, k1 = kk.y * iv.y;
                float k2 = kk.z * iv.z, k3 = kk.w * iv.w;
                a  += k0 * vv.x + k1 * vv.y + k2 * vv.z + k3 * vv.w;
                ks += (k0 + k1) + (k2 + k3);
                vs += (vv.x + vv.y) + (vv.z + vv.w);
            }
            kvacc[(h * 16 + m) * 16 + cc] = a;
            if (cc == 0) ksum[h * 16 + m] = ks;
            if (m == 0)  vsum[h * 16 + cc] = vs;
        }
        // next iteration's weight-stage sync orders kvacc reads vs next GEMM store
    }

    // =============== Phase B: Q per head -> output ===============
    load_tile(x1);

    for (int h = 0; h < NHm; ++h) {
        // stage 16 Wq rows for this head
        for (int idx = t; idx < 16 * C; idx += THREADS) {
            int j = idx >> 7, c = idx & 127;
            wsa[j * WS_STRIDE + c] = Wq[(h * 16 + j) * C + c];
        }
        __syncthreads();

        // GEMM: q[j][n] = sum_c Wq[j][c] * x1[c][n]
        {
            const int j  = t & 15;
            const int ng = t >> 4;  // 0..31, 8 pixels each
            float acc[8];
#pragma unroll
            for (int p = 0; p < 8; ++p) acc[p] = 0.f;
            const float* wrow  = wsa + j * WS_STRIDE;
            const float* xbase = xs + ng * 8;
#pragma unroll 4
            for (int c = 0; c < C; ++c) {
                float wv = wrow[c];
                const float4* xp = reinterpret_cast<const float4*>(xbase + c * NPix);
                float4 a0 = xp[0], a1 = xp[1];
                acc[0] += wv * a0.x; acc[1] += wv * a0.y; acc[2] += wv * a0.z; acc[3] += wv * a0.w;
                acc[4] += wv * a1.x; acc[5] += wv * a1.y; acc[6] += wv * a1.z; acc[7] += wv * a1.w;
            }
            float* qd = kvh + j * KVH_STRIDE + ng * 8;
#pragma unroll
            for (int p = 0; p < 8; ++p) qd[p] = acc[p];
        }
        __syncthreads();

        // epilogue: normalize q, tailor, out[c][n] = (q_n . kv_acc[:,c] + vsum[c]) * tailor[n]
        {
            const int n  = t >> 1;
            const int hf = t & 1;   // which 8-channel half this thread emits
            float qv[16];
            float ss = 0.f;
#pragma unroll
            for (int dd = 0; dd < 16; ++dd) {
                float q = kvh[dd * KVH_STRIDE + n];
                qv[dd] = q;
                ss += q * q;
            }
            float inv = rsqrtf(ss);
            float dot = 0.f;
#pragma unroll
            for (int dd = 0; dd < 16; ++dd) {
                qv[dd] *= inv;
                dot += qv[dd] * (ksum[h * 16 + dd] + EPSf);
            }
            float tail = 1.0f / (256.0f + dot);

            float o[8];
#pragma unroll
            for (int c2 = 0; c2 < 8; ++c2) o[c2] = vsum[h * 16 + hf * 8 + c2];
#pragma unroll
            for (int m2 = 0; m2 < 16; ++m2) {
                float q = qv[m2];
                const float* kr = kvacc + (h * 16 + m2) * 16 + hf * 8;
#pragma unroll
                for (int c2 = 0; c2 < 8; ++c2) o[c2] += q * kr[c2];
            }

            const int r = n >> 4, s2 = n & 15;
            const size_t g0 = base + (size_t)(h * 16 + hf * 8) * CH_STRIDE
                            + (size_t)r * Wdim + s2;
#pragma unroll
            for (int c2 = 0; c2 < 8; ++c2)
                out[g0 + (size_t)c2 * CH_STRIDE] = o[c2] * tail;
        }
        // next iteration's weight-stage sync orders epilogue reads vs next GEMM store
    }
}

extern "C" void kernel_launch(void* const* d_in, const int* in_sizes, int n_in,
                              void* d_out, int out_size) {
    const float* x1  = (const float*)d_in[0];
    const float* x2  = (const float*)d_in[1];
    const float* Wq  = (const float*)d_in[2];
    const float* Wkv = (const float*)d_in[3];
    float* out = (float*)d_out;

    cudaFuncSetAttribute(lwm_kernel, cudaFuncAttributeMaxDynamicSharedMemorySize, SMEM_BYTES);
    lwm_kernel<<<NWin, THREADS, SMEM_BYTES>>>(x1, x2, Wq, Wkv, out);
}

// round 5
// speedup vs baseline: 1.2854x; 1.2854x over previous
#include <cuda_runtime.h>
#include <math.h>

// LWM cross attention, fully fused: per-window 1x1-conv GEMMs (q, kv) +
// linear-attention epilogue. One CTA per 16x16 window.
// R2: 4x4 register-tiled GEMMs with transposed weight stage (2 B/FMA LDS),
//     Q phase processes 2 heads per iteration so all 512 threads work.

namespace {
constexpr int Bn    = 8;
constexpr int C     = 128;
constexpr int Hdim  = 256;
constexpr int Wdim  = 256;
constexpr int NHm   = 8;
constexpr int D     = 16;     // head dim
constexpr int WSz   = 16;     // window size
constexpr int NPix  = 256;    // pixels per window
constexpr int NWin  = Bn * 16 * 16;  // 2048
constexpr int THREADS = 512;
constexpr float EPSf = 1e-6f;

constexpr int KVH_STRIDE = 260;  // 32x256 head buffer rows (16B-aligned)
constexpr int WT_STRIDE  = 36;   // transposed weight stage: wt[c][j], 16B-aligned rows

// shared memory layout (in floats)
constexpr int OFF_XS    = 0;                         // x tile [128][256]
constexpr int OFF_KVH   = OFF_XS + C * NPix;         // head buffer [32][260]
constexpr int OFF_WSA   = OFF_KVH + 32 * KVH_STRIDE; // weight stage [128][36] (transposed)
constexpr int OFF_INV   = OFF_WSA + C * WT_STRIDE;   // per-pixel 1/||k|| [256]
constexpr int OFF_KVACC = OFF_INV + NPix;            // kv_acc [8][16][16]
constexpr int OFF_KSUM  = OFF_KVACC + NHm * D * D;   // ksum [8][16]
constexpr int OFF_VSUM  = OFF_KSUM + NHm * D;        // vsum [8][16]
constexpr int SMEM_FLOATS = OFF_VSUM + NHm * D;      // 48256
constexpr int SMEM_BYTES  = SMEM_FLOATS * 4;         // 193024
}

__global__ void __launch_bounds__(THREADS, 1)
lwm_kernel(const float* __restrict__ x1, const float* __restrict__ x2,
           const float* __restrict__ Wq, const float* __restrict__ Wkv,
           float* __restrict__ out)
{
    extern __shared__ float sm[];
    float* xs    = sm + OFF_XS;
    float* kvh   = sm + OFF_KVH;
    float* wsa   = sm + OFF_WSA;
    float* invb  = sm + OFF_INV;
    float* kvacc = sm + OFF_KVACC;
    float* ksum  = sm + OFF_KSUM;
    float* vsum  = sm + OFF_VSUM;

    const int win = blockIdx.x;
    const int wx  = win & 15;
    const int wy  = (win >> 4) & 15;
    const int b   = win >> 8;
    const int t   = threadIdx.x;
    const int lane = t & 31;
    const int warp = t >> 5;

    const size_t base = (size_t)b * (C * Hdim * Wdim)
                      + (size_t)(wy * WSz) * Wdim + (size_t)(wx * WSz);
    const int CH_STRIDE = Hdim * Wdim;  // 65536

    // ---- tile loader: x[c][n] for this window, float4 vectorized ----
    auto load_tile = [&](const float* __restrict__ src) {
        for (int idx = t; idx < (C * NPix) / 4; idx += THREADS) {
            int c  = idx >> 6;
            int n4 = (idx & 63) << 2;
            int r  = n4 >> 4, s = n4 & 15;
            float4 v = *reinterpret_cast<const float4*>(
                src + base + (size_t)c * CH_STRIDE + r * Wdim + s);
            *reinterpret_cast<float4*>(xs + c * NPix + n4) = v;
        }
    };

    // ---- 32x256 GEMM from transposed weight stage into kvh ----
    // thread tile: 4 j x 4 n.  lane -> (jt = lane&7, nt = lane>>3), warp -> 16-px n-block
    auto gemm32 = [&]() {
        const int jt = lane & 7;
        const int nt = lane >> 3;
        const int n0 = warp * 16 + nt * 4;
        float a0x=0.f,a0y=0.f,a0z=0.f,a0w=0.f;
        float a1x=0.f,a1y=0.f,a1z=0.f,a1w=0.f;
        float a2x=0.f,a2y=0.f,a2z=0.f,a2w=0.f;
        float a3x=0.f,a3y=0.f,a3z=0.f,a3w=0.f;
        const float* wp = wsa + jt * 4;
        const float* xp = xs + n0;
#pragma unroll 4
        for (int c = 0; c < C; ++c) {
            float4 w4 = *reinterpret_cast<const float4*>(wp + c * WT_STRIDE);
            float4 x4 = *reinterpret_cast<const float4*>(xp + c * NPix);
            a0x += w4.x * x4.x; a0y += w4.x * x4.y; a0z += w4.x * x4.z; a0w += w4.x * x4.w;
            a1x += w4.y * x4.x; a1y += w4.y * x4.y; a1z += w4.y * x4.z; a1w += w4.y * x4.w;
            a2x += w4.z * x4.x; a2y += w4.z * x4.y; a2z += w4.z * x4.z; a2w += w4.z * x4.w;
            a3x += w4.w * x4.x; a3y += w4.w * x4.y; a3z += w4.w * x4.z; a3w += w4.w * x4.w;
        }
        float* kd = kvh + (jt * 4) * KVH_STRIDE + n0;
        *reinterpret_cast<float4*>(kd)                  = make_float4(a0x,a0y,a0z,a0w);
        *reinterpret_cast<float4*>(kd + KVH_STRIDE)     = make_float4(a1x,a1y,a1z,a1w);
        *reinterpret_cast<float4*>(kd + 2*KVH_STRIDE)   = make_float4(a2x,a2y,a2z,a2w);
        *reinterpret_cast<float4*>(kd + 3*KVH_STRIDE)   = make_float4(a3x,a3y,a3z,a3w);
    };

    // =============== Phase A: K/V per head -> summaries ===============
    load_tile(x2);

    for (int h = 0; h < NHm; ++h) {
        // stage transposed weights: 16 K rows + 16 V rows of this head
        for (int idx = t; idx < 32 * C; idx += THREADS) {
            int j = idx >> 7, c = idx & 127;
            int row = (j < 16) ? (h * 16 + j) : (C + h * 16 + (j - 16));
            wsa[c * WT_STRIDE + j] = Wkv[row * C + c];
        }
        __syncthreads();

        gemm32();
        __syncthreads();

        // per-pixel inverse norm of k column
        if (t < NPix) {
            float ss = 0.f;
#pragma unroll
            for (int dd = 0; dd < 16; ++dd) {
                float kk = kvh[dd * KVH_STRIDE + t];
                ss += kk * kk;
            }
            invb[t] = rsqrtf(ss);
        }
        __syncthreads();

        // kv_acc[m][c] = sum_n k_norm[m,n] * v[c,n]; ksum, vsum folded in
        if (t < 256) {
            const int m  = t >> 4;
            const int cc = t & 15;
            const float4* kp = reinterpret_cast<const float4*>(kvh + m * KVH_STRIDE);
            const float4* vp = reinterpret_cast<const float4*>(kvh + (16 + cc) * KVH_STRIDE);
            const float4* ip = reinterpret_cast<const float4*>(invb);
            float a = 0.f, ks = 0.f, vs = 0.f;
#pragma unroll 4
            for (int qn = 0; qn < 64; ++qn) {
                float4 kk = kp[qn], vv = vp[qn], iv = ip[qn];
                float k0 = kk.x * iv.x, k1 = kk.y * iv.y;
                float k2 = kk.z * iv.z, k3 = kk.w * iv.w;
                a  += k0 * vv.x + k1 * vv.y + k2 * vv.z + k3 * vv.w;
                ks += (k0 + k1) + (k2 + k3);
                vs += (vv.x + vv.y) + (vv.z + vv.w);
            }
            kvacc[(h * 16 + m) * 16 + cc] = a;
            if (cc == 0) ksum[h * 16 + m] = ks;
            if (m == 0)  vsum[h * 16 + cc] = vs;
        }
        // next iteration's post-stage sync orders kvacc reads vs next GEMM stores
    }

    // =============== Phase B: Q, two heads per iteration ===============
    load_tile(x1);

    for (int hp = 0; hp < NHm / 2; ++hp) {
        // stage transposed Wq rows [hp*32, hp*32+32) = heads 2hp and 2hp+1
        for (int idx = t; idx < 32 * C; idx += THREADS) {
            int j = idx >> 7, c = idx & 127;
            wsa[c * WT_STRIDE + j] = Wq[(hp * 32 + j) * C + c];
        }
        __syncthreads();

        gemm32();   // q rows: j<16 -> head 2hp, j>=16 -> head 2hp+1
        __syncthreads();

        // epilogue: one (pixel, head) per thread, full 16 output channels
        {
            const int n    = t >> 1;
            const int hh   = t & 1;
            const int head = hp * 2 + hh;

            float qv[16];
            float ss = 0.f;
#pragma unroll
            for (int dd = 0; dd < 16; ++dd) {
                float q = kvh[(hh * 16 + dd) * KVH_STRIDE + n];
                qv[dd] = q;
                ss += q * q;
            }
            float inv = rsqrtf(ss);
            float dot = 0.f;
#pragma unroll
            for (int dd = 0; dd < 16; ++dd) {
                qv[dd] *= inv;
                dot += qv[dd] * (ksum[head * 16 + dd] + EPSf);
            }
            float tail = 1.0f / (256.0f + dot);

            float o[16];
            {
                const float4* vs4 = reinterpret_cast<const float4*>(vsum + head * 16);
#pragma unroll
                for (int q4 = 0; q4 < 4; ++q4) {
                    float4 v = vs4[q4];
                    o[q4*4+0] = v.x; o[q4*4+1] = v.y; o[q4*4+2] = v.z; o[q4*4+3] = v.w;
                }
            }
#pragma unroll
            for (int m2 = 0; m2 < 16; ++m2) {
                float q = qv[m2];
                const float4* kr = reinterpret_cast<const float4*>(kvacc + (head * 16 + m2) * 16);
#pragma unroll
                for (int q4 = 0; q4 < 4; ++q4) {
                    float4 v = kr[q4];
                    o[q4*4+0] += q * v.x; o[q4*4+1] += q * v.y;
                    o[q4*4+2] += q * v.z; o[q4*4+3] += q * v.w;
                }
            }

            const int r = n >> 4, s2 = n & 15;
            const size_t g0 = base + (size_t)(head * 16) * CH_STRIDE
                            + (size_t)r * Wdim + s2;
#pragma unroll
            for (int c2 = 0; c2 < 16; ++c2)
                out[g0 + (size_t)c2 * CH_STRIDE] = o[c2] * tail;
        }
        // next iteration's post-stage sync orders epilogue kvh reads vs next GEMM stores
    }
}

extern "C" void kernel_launch(void* const* d_in, const int* in_sizes, int n_in,
                              void* d_out, int out_size) {
    const float* x1  = (const float*)d_in[0];
    const float* x2  = (const float*)d_in[1];
    const float* Wq  = (const float*)d_in[2];
    const float* Wkv = (const float*)d_in[3];
    float* out = (float*)d_out;

    cudaFuncSetAttribute(lwm_kernel, cudaFuncAttributeMaxDynamicSharedMemorySize, SMEM_BYTES);
    lwm_kernel<<<NWin, THREADS, SMEM_BYTES>>>(x1, x2, Wq, Wkv, out);
}